// round 8
// baseline (speedup 1.0000x reference)
#include <cuda_runtime.h>

// ============================================================================
// DIAGNOSTIC ROUND: kernel_launch issues accum TWICE (idempotent: plain
// overwriting stores) so the ncu -s 5 -c 1 capture window lands on the hot
// accum_kernel instead of final_kernel (launch cycle length 3 -> 2/3 odds).
// Timing regresses this round by ~1x accum; structure is otherwise the
// proven R7 kernel (passed, rel_err 4.5e-7).
// ============================================================================

#define BN 256
#define CN 1024
#define HW 169        // 13*13
#define SPLIT 2       // -> 512 accum blocks = single wave
#define Z_CONST 17.079468445347132f   // 2*pi*e
#define EPS_CONST 1e-6f

// Per-(b, split, moment, channel) partials: S, Sx, Sy, Sr=Σ(wx^2+wy^2)f.
// 256*2*4*1024 floats = 8.4 MB.
__device__ float g_part[BN * SPLIT * 4 * CN];

// packed fp32x2 ops (PTX-only; ptxas won't auto-fuse)
#define PACK2(d, lo, hi)   asm("mov.b64 %0, {%1, %2};" : "=l"(d) : "f"(lo), "f"(hi))
#define ADD2(d, a, b)      asm("add.rn.f32x2 %0, %1, %2;" : "=l"(d) : "l"(a), "l"(b))
#define FMA2(d, a, b, c)   asm("fma.rn.f32x2 %0, %1, %2, %3;" : "=l"(d) : "l"(a), "l"(b), "l"(c))

// ---------------------------------------------------------------------------
// Kernel 1: 256 thr/block, thread owns channels [4t,4t+4).
// Distance-2 prefetch via buf[k&1] ring; pipeline:
// E(exp k) / L(load k+2) / warp+smem partial k / F(accumulate k-1).
// ---------------------------------------------------------------------------
__global__ __launch_bounds__(256, 5) void accum_kernel(const float* __restrict__ x,
                                                       float* __restrict__ out) {
    if (blockIdx.x == 0 && threadIdx.x == 0) out[0] = 0.0f;

    const int b    = blockIdx.x >> 1;
    const int sp   = blockIdx.x & 1;
    const int p0   = sp ? 85 : 0;
    const int p1   = sp ? HW : 85;
    const int n    = p1 - p0;
    const int tid  = threadIdx.x;
    const int wid  = tid >> 5;
    const int lane = tid & 31;

    __shared__ __align__(16) float red[2][8];  // [buf][warp]

    const float4* __restrict__ xb = (const float4*)(x + (size_t)b * HW * CN) + tid;

    unsigned long long S[2]  = {0, 0};
    unsigned long long Sx[2] = {0, 0};
    unsigned long long Sy[2] = {0, 0};
    unsigned long long Sr[2] = {0, 0};

    const int h0 = p0 / 13;
    float wx = (float)(h0 + 1);
    float wy = (float)(p0 - h0 * 13 + 1);

    float4 buf[2];
    buf[0] = __ldcs(xb + (size_t)p0 * 256);
    buf[1] = (n > 1) ? __ldcs(xb + (size_t)(p0 + 1) * 256) : buf[0];

    unsigned long long pe0 = 0, pe1 = 0;

#pragma unroll 2
    for (int k = 0; k < n; ++k) {
        float e0 = __expf(buf[k & 1].x), e1 = __expf(buf[k & 1].y);
        float e2 = __expf(buf[k & 1].z), e3 = __expf(buf[k & 1].w);

        if (k + 2 < n) buf[k & 1] = __ldcs(xb + (size_t)(p0 + k + 2) * 256);

        unsigned long long ea, eb;
        PACK2(ea, e0, e1); PACK2(eb, e2, e3);

        float s = (e0 + e1) + (e2 + e3);
#pragma unroll
        for (int m = 16; m > 0; m >>= 1)
            s += __shfl_xor_sync(0xffffffffu, s, m);
        if (lane == 0) red[k & 1][wid] = s;

        if (k >= 1) {
            const float4* rp = (const float4*)red[(k - 1) & 1];
            float4 ra = rp[0], rb = rp[1];
            float den = ((ra.x + ra.y) + (ra.z + ra.w))
                      + ((rb.x + rb.y) + (rb.z + rb.w));
            float inv = __fdividef(1.0f, den);
            float w1  = inv * wx;
            float w2  = inv * wy;
            float wr  = fmaf(wx, wx, wy * wy) * inv;
            unsigned long long inv2, w12, w22, wr2;
            PACK2(inv2, inv, inv); PACK2(w12, w1, w1);
            PACK2(w22, w2, w2);    PACK2(wr2, wr, wr);
            FMA2(S[0],  inv2, pe0, S[0]);  FMA2(S[1],  inv2, pe1, S[1]);
            FMA2(Sx[0], w12,  pe0, Sx[0]); FMA2(Sx[1], w12,  pe1, Sx[1]);
            FMA2(Sy[0], w22,  pe0, Sy[0]); FMA2(Sy[1], w22,  pe1, Sy[1]);
            FMA2(Sr[0], wr2,  pe0, Sr[0]); FMA2(Sr[1], wr2,  pe1, Sr[1]);
            wy += 1.0f;
            if (wy > 13.0f) { wy = 1.0f; wx += 1.0f; }
        }

        __syncthreads();

        pe0 = ea; pe1 = eb;
    }

    // epilogue: final position n-1
    {
        const float4* rp = (const float4*)red[(n - 1) & 1];
        float4 ra = rp[0], rb = rp[1];
        float den = ((ra.x + ra.y) + (ra.z + ra.w))
                  + ((rb.x + rb.y) + (rb.z + rb.w));
        float inv = __fdividef(1.0f, den);
        float w1  = inv * wx;
        float w2  = inv * wy;
        float wr  = fmaf(wx, wx, wy * wy) * inv;
        unsigned long long inv2, w12, w22, wr2;
        PACK2(inv2, inv, inv); PACK2(w12, w1, w1);
        PACK2(w22, w2, w2);    PACK2(wr2, wr, wr);
        FMA2(S[0],  inv2, pe0, S[0]);  FMA2(S[1],  inv2, pe1, S[1]);
        FMA2(Sx[0], w12,  pe0, Sx[0]); FMA2(Sx[1], w12,  pe1, Sx[1]);
        FMA2(Sy[0], w22,  pe0, Sy[0]); FMA2(Sy[1], w22,  pe1, Sy[1]);
        FMA2(Sr[0], wr2,  pe0, Sr[0]); FMA2(Sr[1], wr2,  pe1, Sr[1]);
    }

    float* gp = g_part + (size_t)(b * SPLIT + sp) * 4 * CN;
    const int c4 = tid << 2;
    *(ulonglong2*)(gp + 0 * CN + c4) = make_ulonglong2(S[0],  S[1]);
    *(ulonglong2*)(gp + 1 * CN + c4) = make_ulonglong2(Sx[0], Sx[1]);
    *(ulonglong2*)(gp + 2 * CN + c4) = make_ulonglong2(Sy[0], Sy[1]);
    *(ulonglong2*)(gp + 3 * CN + c4) = make_ulonglong2(Sr[0], Sr[1]);
}

// ---------------------------------------------------------------------------
// Kernel 2: sum splits, per-(b,c) det, block reduce, atomicAdd scalar.
// ---------------------------------------------------------------------------
__global__ __launch_bounds__(256) void final_kernel(float* __restrict__ out) {
    const int b   = blockIdx.x;
    const int tid = threadIdx.x;
    const int c4  = tid << 2;

    const float* g0 = g_part + (size_t)(b * SPLIT + 0) * 4 * CN;
    const float* g1 = g_part + (size_t)(b * SPLIT + 1) * 4 * CN;
    float4 a0 = *(const float4*)(g0 + 0 * CN + c4);
    float4 a1 = *(const float4*)(g0 + 1 * CN + c4);
    float4 a2 = *(const float4*)(g0 + 2 * CN + c4);
    float4 a3 = *(const float4*)(g0 + 3 * CN + c4);
    float4 b0 = *(const float4*)(g1 + 0 * CN + c4);
    float4 b1 = *(const float4*)(g1 + 1 * CN + c4);
    float4 b2 = *(const float4*)(g1 + 2 * CN + c4);
    float4 b3 = *(const float4*)(g1 + 3 * CN + c4);

    float m0[4] = {a0.x + b0.x, a0.y + b0.y, a0.z + b0.z, a0.w + b0.w};
    float m1[4] = {a1.x + b1.x, a1.y + b1.y, a1.z + b1.z, a1.w + b1.w};
    float m2[4] = {a2.x + b2.x, a2.y + b2.y, a2.z + b2.z, a2.w + b2.w};
    float m3[4] = {a3.x + b3.x, a3.y + b3.y, a3.z + b3.z, a3.w + b3.w};

    float acc = 0.0f;
#pragma unroll
    for (int j = 0; j < 4; ++j) {
        float s     = m0[j] + EPS_CONST;
        float inv_s = 1.0f / s;
        float mx    = m1[j] * inv_s;
        float my    = m2[j] * inv_s;
        float num   = m3[j] - 2.0f * (mx * m1[j] + my * m2[j])
                    + (mx * mx + my * my) * m0[j];
        float d     = num * inv_s * (1.0f / 169.0f);
        acc = fmaf(d * d, Z_CONST, acc);
    }

#pragma unroll
    for (int msk = 16; msk > 0; msk >>= 1)
        acc += __shfl_xor_sync(0xffffffffu, acc, msk);

    __shared__ float wsum[8];
    if ((tid & 31) == 0) wsum[tid >> 5] = acc;
    __syncthreads();
    if (tid == 0) {
        float t = ((wsum[0] + wsum[1]) + (wsum[2] + wsum[3]))
                + ((wsum[4] + wsum[5]) + (wsum[6] + wsum[7]));
        atomicAdd(out, t * (1.0f / (float)(BN * CN)));
    }
}

// ---------------------------------------------------------------------------
extern "C" void kernel_launch(void* const* d_in, const int* in_sizes, int n_in,
                              void* d_out, int out_size) {
    const float* x = (const float*)d_in[0];
    float* out = (float*)d_out;

    // accum issued twice (idempotent overwrite) purely so the profiler's
    // skip-5-capture-1 window lands on accum_kernel with 2/3 probability.
    accum_kernel<<<BN * SPLIT, 256>>>(x, out);
    accum_kernel<<<BN * SPLIT, 256>>>(x, out);
    final_kernel<<<BN, 256>>>(out);
}

// round 10
// speedup vs baseline: 2.4849x; 2.4849x over previous
#include <cuda_runtime.h>

#define BN 256
#define CN 1024
#define HW 169        // 13*13
#define SPLIT 4       // -> 1024 accum blocks
#define Z_CONST 17.079468445347132f   // 2*pi*e
#define EPS_CONST 1e-6f

// Per-(b, split, moment, channel) partials: S, Sx, Sy, Sr=Σ(wx^2+wy^2)f.
// 256*4*4*1024 floats = 16.8 MB.
__device__ float g_part[BN * SPLIT * 4 * CN];

// packed fp32x2 ops (PTX-only; ptxas won't auto-fuse)
#define PACK2(d, lo, hi)   asm("mov.b64 %0, {%1, %2};" : "=l"(d) : "f"(lo), "f"(hi))
#define FMA2(d, a, b, c)   asm("fma.rn.f32x2 %0, %1, %2, %3;" : "=l"(d) : "l"(a), "l"(b), "l"(c))

// ---------------------------------------------------------------------------
// Kernel 1: 256 thr/block, thread owns channels [4t,4t+4).
// FOUR positions per barrier: 16 exps, 4 interleaved shfl chains, one
// __syncthreads, then 4 denominators + 32 FMA2. Next group's 4 loads issued
// right after the exps consume the buffers (MLP=4, ~2 group-bodies of cover).
// Tail positions are clamped (inv forced to 0 -> no-op accumulation).
// ---------------------------------------------------------------------------
__global__ __launch_bounds__(256, 3) void accum_kernel(const float* __restrict__ x,
                                                       float* __restrict__ out) {
    if (blockIdx.x == 0 && threadIdx.x == 0) out[0] = 0.0f;

    const int b    = blockIdx.x >> 2;
    const int sp   = blockIdx.x & 3;
    const int p0   = (sp * HW) >> 2;           // 0,42,84,126
    const int p1   = ((sp + 1) * HW) >> 2;     // 42,84,126,169
    const int tid  = threadIdx.x;
    const int wid  = tid >> 5;
    const int lane = tid & 31;

    __shared__ __align__(16) float red[2][4][8];   // [buf][pos-in-group][warp]

    const float4* __restrict__ xb = (const float4*)(x + (size_t)b * HW * CN) + tid;

    unsigned long long S[2]  = {0, 0};
    unsigned long long Sx[2] = {0, 0};
    unsigned long long Sy[2] = {0, 0};
    unsigned long long Sr[2] = {0, 0};

    const int n       = p1 - p0;
    const int ngroups = (n + 3) >> 2;

    // prologue: load group 0 (clamped)
    float4 buf[4];
#pragma unroll
    for (int j = 0; j < 4; ++j) {
        int p = p0 + j; if (p >= p1) p = p1 - 1;
        buf[j] = __ldcs(xb + (size_t)p * 256);
    }

    for (int g = 0; g < ngroups; ++g) {
        const int pbase = p0 + 4 * g;

        // ---- exps for 4 positions (consume bufs) ----
        float e[16];
#pragma unroll
        for (int j = 0; j < 4; ++j) {
            e[4 * j + 0] = __expf(buf[j].x);
            e[4 * j + 1] = __expf(buf[j].y);
            e[4 * j + 2] = __expf(buf[j].z);
            e[4 * j + 3] = __expf(buf[j].w);
        }

        // ---- prefetch group g+1 (WAR overwrite of consumed bufs) ----
        if (g + 1 < ngroups) {
#pragma unroll
            for (int j = 0; j < 4; ++j) {
                int p = pbase + 4 + j; if (p >= p1) p = p1 - 1;
                buf[j] = __ldcs(xb + (size_t)p * 256);
            }
        }

        // ---- 4 interleaved warp-reduction chains ----
        float s0 = (e[0]  + e[1])  + (e[2]  + e[3]);
        float s1 = (e[4]  + e[5])  + (e[6]  + e[7]);
        float s2 = (e[8]  + e[9])  + (e[10] + e[11]);
        float s3 = (e[12] + e[13]) + (e[14] + e[15]);
#pragma unroll
        for (int m = 16; m > 0; m >>= 1) {
            s0 += __shfl_xor_sync(0xffffffffu, s0, m);
            s1 += __shfl_xor_sync(0xffffffffu, s1, m);
            s2 += __shfl_xor_sync(0xffffffffu, s2, m);
            s3 += __shfl_xor_sync(0xffffffffu, s3, m);
        }
        if (lane == 0) {
            red[g & 1][0][wid] = s0;
            red[g & 1][1][wid] = s1;
            red[g & 1][2][wid] = s2;
            red[g & 1][3][wid] = s3;
        }
        __syncthreads();

        // ---- denominators + accumulate 4 positions ----
#pragma unroll
        for (int j = 0; j < 4; ++j) {
            const float4* rp = (const float4*)red[g & 1][j];
            float4 ra = rp[0], rb = rp[1];
            float den = ((ra.x + ra.y) + (ra.z + ra.w))
                      + ((rb.x + rb.y) + (rb.z + rb.w));
            const int p = pbase + j;
            float inv = (p < p1) ? __fdividef(1.0f, den) : 0.0f;
            const unsigned pc = (p < p1) ? (unsigned)p : 0u;
            const unsigned h  = (pc * 5042u) >> 16;         // floor(p/13), p<169
            float wxj = (float)(h + 1);
            float wyj = (float)(pc - h * 13u + 1u);
            float w1  = inv * wxj;
            float w2  = inv * wyj;
            float wr  = fmaf(wxj, wxj, wyj * wyj) * inv;

            unsigned long long ea, eb, inv2, w12, w22, wr2;
            PACK2(ea, e[4 * j + 0], e[4 * j + 1]);
            PACK2(eb, e[4 * j + 2], e[4 * j + 3]);
            PACK2(inv2, inv, inv); PACK2(w12, w1, w1);
            PACK2(w22, w2, w2);    PACK2(wr2, wr, wr);

            FMA2(S[0],  inv2, ea, S[0]);  FMA2(S[1],  inv2, eb, S[1]);
            FMA2(Sx[0], w12,  ea, Sx[0]); FMA2(Sx[1], w12,  eb, Sx[1]);
            FMA2(Sy[0], w22,  ea, Sy[0]); FMA2(Sy[1], w22,  eb, Sy[1]);
            FMA2(Sr[0], wr2,  ea, Sr[0]); FMA2(Sr[1], wr2,  eb, Sr[1]);
        }
    }

    // ---- coalesced partial stores: [B][SPLIT][4][CN] ----
    float* gp = g_part + (size_t)(b * SPLIT + sp) * 4 * CN;
    const int c4 = tid << 2;
    *(ulonglong2*)(gp + 0 * CN + c4) = make_ulonglong2(S[0],  S[1]);
    *(ulonglong2*)(gp + 1 * CN + c4) = make_ulonglong2(Sx[0], Sx[1]);
    *(ulonglong2*)(gp + 2 * CN + c4) = make_ulonglong2(Sy[0], Sy[1]);
    *(ulonglong2*)(gp + 3 * CN + c4) = make_ulonglong2(Sr[0], Sr[1]);
}

// ---------------------------------------------------------------------------
// Kernel 2: sum splits, per-(b,c) det, block reduce, one RED.add per block.
// 2048 blocks x 128 thr; thread owns ONE channel (fully coalesced loads).
// ---------------------------------------------------------------------------
__global__ __launch_bounds__(128) void final_kernel(float* __restrict__ out) {
    const int bb  = blockIdx.x;          // 0..2047: 8 blocks per batch
    const int b   = bb >> 3;
    const int c   = ((bb & 7) << 7) + threadIdx.x;
    const int tid = threadIdx.x;

    float m0 = 0.f, m1 = 0.f, m2 = 0.f, m3 = 0.f;
#pragma unroll
    for (int s = 0; s < SPLIT; ++s) {
        const float* gs = g_part + (size_t)(b * SPLIT + s) * 4 * CN;
        m0 += gs[0 * CN + c];
        m1 += gs[1 * CN + c];
        m2 += gs[2 * CN + c];
        m3 += gs[3 * CN + c];
    }

    float s     = m0 + EPS_CONST;
    float inv_s = 1.0f / s;
    float mx    = m1 * inv_s;
    float my    = m2 * inv_s;
    float num   = m3 - 2.0f * (mx * m1 + my * m2) + (mx * mx + my * my) * m0;
    float d     = num * inv_s * (1.0f / 169.0f);
    float acc   = d * d * Z_CONST;

#pragma unroll
    for (int msk = 16; msk > 0; msk >>= 1)
        acc += __shfl_xor_sync(0xffffffffu, acc, msk);

    __shared__ float wsum[4];
    if ((tid & 31) == 0) wsum[tid >> 5] = acc;
    __syncthreads();
    if (tid == 0) {
        float t = (wsum[0] + wsum[1]) + (wsum[2] + wsum[3]);
        atomicAdd(out, t * (1.0f / (float)(BN * CN)));
    }
}

// ---------------------------------------------------------------------------
extern "C" void kernel_launch(void* const* d_in, const int* in_sizes, int n_in,
                              void* d_out, int out_size) {
    const float* x = (const float*)d_in[0];
    float* out = (float*)d_out;

    accum_kernel<<<BN * SPLIT, 256>>>(x, out);
    final_kernel<<<2048, 128>>>(out);
}